// round 1
// baseline (speedup 1.0000x reference)
#include <cuda_runtime.h>

// Problem constants
#define G_   512
#define N_   512
#define E_   2048
#define F_   64
#define D1_  128
#define D2_  64
#define L_   32
#define P_   16384

// ---------------- device scratch (no allocations allowed) ----------------
__device__ float g_t1[G_ * D1_];     // dinv2[n] * (emb[n,:] @ conv1_W)
__device__ float g_t2[G_ * D2_];     // dinv2[n] * (relu_out[n,:] @ mu_W)
__device__ int   g_cnt[G_];
__device__ int   g_off[G_ + 1];
__device__ int   g_fill[G_];
__device__ float g_dinv2[G_];
__device__ int   g_srcbuf[P_];

// ---------------- CSR build for the graph-level (VGAE) adjacency ----------
__global__ void zero_kernel() {
    int t = threadIdx.x;
    g_cnt[t] = 0;
    g_fill[t] = 0;
}

__global__ void count_kernel(const int* __restrict__ pos_edges) {
    int e = blockIdx.x * blockDim.x + threadIdx.x;
    atomicAdd(&g_cnt[pos_edges[P_ + e]], 1);   // dst half
}

__global__ void scan_kernel() {
    __shared__ int s[G_];
    int tid = threadIdx.x;
    int c = g_cnt[tid];
    g_dinv2[tid] = rsqrtf((float)(c + 1));     // +1 self loop
    s[tid] = c;
    __syncthreads();
    // Hillis-Steele inclusive scan over 512
    for (int ofs = 1; ofs < G_; ofs <<= 1) {
        int v = (tid >= ofs) ? s[tid - ofs] : 0;
        __syncthreads();
        s[tid] += v;
        __syncthreads();
    }
    g_off[tid + 1] = s[tid];
    if (tid == 0) g_off[0] = 0;
}

__global__ void scatter_kernel(const int* __restrict__ pos_edges) {
    int e = blockIdx.x * blockDim.x + threadIdx.x;
    int d = pos_edges[P_ + e];
    int p = g_off[d] + atomicAdd(&g_fill[d], 1);
    g_srcbuf[p] = pos_edges[e];                // src
}

// ---------------- SAGE per graph, collapsed to rank-1 form ----------------
// emb[g,:] = ((w^T X_g) @ W1 + 512*b1) / 16
// then immediately t1[g,:] = dinv2[g] * (emb[g,:] @ conv1_W)
__global__ void __launch_bounds__(512) sage_kernel(
    const float* __restrict__ features,
    const int*   __restrict__ edges,
    const float* __restrict__ W1,
    const float* __restrict__ b1,
    const float* __restrict__ conv1_W)
{
    const int g   = blockIdx.x;
    const int tid = threadIdx.x;

    __shared__ float s_dinv[N_];
    __shared__ float s_acc[N_];     // sdst then w
    __shared__ int   s_deg[N_];
    __shared__ float s_v[512];      // 8 groups x 64
    __shared__ float s_emb[D1_];

    const int* src = edges + (size_t)g * 2 * E_;
    const int* dst = src + E_;

    s_deg[tid] = 1;                 // self loop
    s_acc[tid] = 0.f;
    __syncthreads();

    #pragma unroll
    for (int i = 0; i < E_ / 512; i++) {
        int d = __ldg(&dst[tid + i * 512]);
        atomicAdd(&s_deg[d], 1);
    }
    __syncthreads();
    s_dinv[tid] = rsqrtf((float)s_deg[tid]);
    __syncthreads();

    #pragma unroll
    for (int i = 0; i < E_ / 512; i++) {
        int e = tid + i * 512;
        int s = __ldg(&src[e]);
        int d = __ldg(&dst[e]);
        atomicAdd(&s_acc[s], s_dinv[d]);
    }
    __syncthreads();
    // w[n] = dinv[n]*(sdst[n] + dinv[n])   (edge term + self-loop term)
    float w = s_dinv[tid] * (s_acc[tid] + s_dinv[tid]);
    s_acc[tid] = w;                 // own-slot rewrite, safe
    __syncthreads();

    // v[f] = sum_n w[n] * x[n,f]   (512 threads: 8 row-groups x 64 f-lanes)
    const int f   = tid & 63;
    const int grp = tid >> 6;
    const float* xg = features + (size_t)g * N_ * F_;
    float acc = 0.f;
    #pragma unroll 8
    for (int n = grp; n < N_; n += 8) {
        acc += s_acc[n] * __ldg(&xg[n * F_ + f]);
    }
    s_v[tid] = acc;
    __syncthreads();
    if (tid < 64) {
        float v = 0.f;
        #pragma unroll
        for (int gr = 0; gr < 8; gr++) v += s_v[gr * 64 + tid];
        s_v[tid] = v;
    }
    __syncthreads();

    // emb[d] = (sum_f v[f]*W1[f,d] + 512*b1[d]) / 16
    if (tid < D1_) {
        float a = 512.0f * __ldg(&b1[tid]);
        #pragma unroll
        for (int ff = 0; ff < F_; ff++)
            a += s_v[ff] * __ldg(&W1[ff * D1_ + tid]);
        s_emb[tid] = a * (1.0f / 16.0f);
    }
    __syncthreads();

    // t1[g,d'] = dinv2[g] * sum_d emb[d] * conv1_W[d,d']
    if (tid < D1_) {
        float dv = __ldg(&g_dinv2[g]);
        float a = 0.f;
        #pragma unroll 8
        for (int d = 0; d < D1_; d++)
            a += s_emb[d] * __ldg(&conv1_W[d * D1_ + tid]);
        g_t1[g * D1_ + tid] = dv * a;
    }
}

// ---------------- conv1 gather + relu + mu matmul (fused) -----------------
// out1[m,d] = relu( dinv2[m]*(sum_{in} t1[src,d] + t1[m,d]) + conv1_b[d] )
// t2[m,d2]  = dinv2[m] * sum_d out1[m,d]*mu_W[d,d2]
__global__ void __launch_bounds__(128) gather1_kernel(
    const float* __restrict__ conv1_b,
    const float* __restrict__ mu_W)
{
    int m = blockIdx.x;
    int d = threadIdx.x;            // 128
    __shared__ float s_row[D1_];

    int beg = g_off[m], end = g_off[m + 1];
    float acc = g_t1[m * D1_ + d];  // self loop
    for (int i = beg; i < end; i++) {
        int s = __ldg(&g_srcbuf[i]);
        acc += g_t1[s * D1_ + d];
    }
    float dv = g_dinv2[m];
    s_row[d] = fmaxf(dv * acc + __ldg(&conv1_b[d]), 0.f);
    __syncthreads();

    if (d < D2_) {
        float a = 0.f;
        #pragma unroll 8
        for (int ff = 0; ff < D1_; ff++)
            a += s_row[ff] * __ldg(&mu_W[ff * D2_ + d]);
        g_t2[m * D2_ + d] = dv * a;
    }
}

// ---------------- mu gather + classifier + log_softmax (fused) ------------
__global__ void __launch_bounds__(64) gather2_kernel(
    const float* __restrict__ mu_b,
    const float* __restrict__ clf_W,
    const float* __restrict__ clf_b,
    float* __restrict__ out)
{
    int m = blockIdx.x;
    int d = threadIdx.x;            // 64
    __shared__ float s_mu[D2_];

    int beg = g_off[m], end = g_off[m + 1];
    float acc = g_t2[m * D2_ + d];  // self loop
    for (int i = beg; i < end; i++) {
        int s = __ldg(&g_srcbuf[i]);
        acc += g_t2[s * D2_ + d];
    }
    s_mu[d] = g_dinv2[m] * acc + __ldg(&mu_b[d]);
    __syncthreads();

    if (d < L_) {                   // warp 0 computes 32 logits + log_softmax
        float a = __ldg(&clf_b[d]);
        #pragma unroll
        for (int ff = 0; ff < D2_; ff++)
            a += s_mu[ff] * __ldg(&clf_W[ff * L_ + d]);
        float mx = a;
        #pragma unroll
        for (int o = 16; o > 0; o >>= 1)
            mx = fmaxf(mx, __shfl_xor_sync(0xffffffffu, mx, o));
        float ex = expf(a - mx);
        float sm = ex;
        #pragma unroll
        for (int o = 16; o > 0; o >>= 1)
            sm += __shfl_xor_sync(0xffffffffu, sm, o);
        out[m * L_ + d] = a - mx - logf(sm);
    }
}

// --------------------------------------------------------------------------
extern "C" void kernel_launch(void* const* d_in, const int* in_sizes, int n_in,
                              void* d_out, int out_size)
{
    const float* features = (const float*)d_in[0];
    const int*   edges    = (const int*)  d_in[1];
    const int*   pos_e    = (const int*)  d_in[2];
    const float* W1       = (const float*)d_in[3];
    const float* b1       = (const float*)d_in[4];
    // d_in[5..8]: fc1_W, fc1_b, fc2_W, fc2_b — mathematically dead (softmax rows sum to 1)
    const float* conv1_W  = (const float*)d_in[9];
    const float* conv1_b  = (const float*)d_in[10];
    const float* mu_W     = (const float*)d_in[11];
    const float* mu_b     = (const float*)d_in[12];
    const float* clf_W    = (const float*)d_in[13];
    const float* clf_b    = (const float*)d_in[14];
    float* out = (float*)d_out;

    zero_kernel   <<<1, 512>>>();
    count_kernel  <<<P_ / 512, 512>>>(pos_e);
    scan_kernel   <<<1, 512>>>();
    scatter_kernel<<<P_ / 512, 512>>>(pos_e);
    sage_kernel   <<<G_, 512>>>(features, edges, W1, b1, conv1_W);
    gather1_kernel<<<G_, 128>>>(conv1_b, mu_W);
    gather2_kernel<<<G_, 64>>>(mu_b, clf_W, clf_b, out);
}

// round 2
// speedup vs baseline: 1.0455x; 1.0455x over previous
#include <cuda_runtime.h>

// Problem constants
#define G_   512
#define N_   512
#define E_   2048
#define F_   64
#define D1_  128
#define D2_  64
#define L_   32
#define P_   16384

// ---------------- device scratch (no allocations allowed) ----------------
__device__ float g_t1[G_ * D1_];     // dinv2[n] * (emb[n,:] @ conv1_W)
__device__ float g_t2[G_ * D2_];     // dinv2[n] * (relu_out[n,:] @ mu_W)
__device__ int   g_off[G_ + 1];
__device__ float g_dinv2[G_];
__device__ int   g_srcbuf[P_];

// ---------------- fused CSR build (one block, smem atomics) ---------------
__global__ void __launch_bounds__(512) build_kernel(const int* __restrict__ pos_edges)
{
    __shared__ int s_cnt[G_];
    __shared__ int s_a[G_];
    __shared__ int s_b[G_];
    __shared__ int s_fill[G_];

    const int tid = threadIdx.x;
    s_cnt[tid] = 0;
    __syncthreads();

    const int4* src4 = (const int4*)pos_edges;
    const int4* dst4 = (const int4*)(pos_edges + P_);

    // ---- count (smem atomics, low contention) ----
    #pragma unroll
    for (int i = tid; i < P_ / 4; i += 512) {
        int4 d = __ldg(&dst4[i]);
        atomicAdd(&s_cnt[d.x], 1);
        atomicAdd(&s_cnt[d.y], 1);
        atomicAdd(&s_cnt[d.z], 1);
        atomicAdd(&s_cnt[d.w], 1);
    }
    __syncthreads();

    const int c = s_cnt[tid];
    g_dinv2[tid] = rsqrtf((float)(c + 1));     // +1 self loop

    // ---- inclusive scan (two-buffer Hillis-Steele over 512) ----
    s_a[tid] = c;
    __syncthreads();
    int* in  = s_a;
    int* out = s_b;
    for (int ofs = 1; ofs < G_; ofs <<= 1) {
        out[tid] = in[tid] + ((tid >= ofs) ? in[tid - ofs] : 0);
        __syncthreads();
        int* t = in; in = out; out = t;
    }
    // 'in' holds inclusive scan
    g_off[tid + 1] = in[tid];
    if (tid == 0) g_off[0] = 0;
    s_fill[tid] = in[tid] - c;                 // exclusive offset
    __syncthreads();

    // ---- scatter (smem fill counters) ----
    #pragma unroll
    for (int i = tid; i < P_ / 4; i += 512) {
        int4 d = __ldg(&dst4[i]);
        int4 s = __ldg(&src4[i]);
        int p0 = atomicAdd(&s_fill[d.x], 1); g_srcbuf[p0] = s.x;
        int p1 = atomicAdd(&s_fill[d.y], 1); g_srcbuf[p1] = s.y;
        int p2 = atomicAdd(&s_fill[d.z], 1); g_srcbuf[p2] = s.z;
        int p3 = atomicAdd(&s_fill[d.w], 1); g_srcbuf[p3] = s.w;
    }
}

// ---------------- SAGE per graph, collapsed to rank-1 form ----------------
// emb[g,:] = ((w^T X_g) @ W1 + 512*b1) / 16
// then t1[g,:] = dinv2[g] * (emb[g,:] @ conv1_W)
__global__ void __launch_bounds__(512) sage_kernel(
    const float* __restrict__ features,
    const int*   __restrict__ edges,
    const float* __restrict__ W1,
    const float* __restrict__ b1,
    const float* __restrict__ conv1_W)
{
    const int g   = blockIdx.x;
    const int tid = threadIdx.x;

    __shared__ float s_dinv[N_];
    __shared__ float s_w[N_];
    __shared__ int   s_deg[N_];
    __shared__ float s_part[32 * F_];   // 32 groups x 64 floats
    __shared__ float s_v[F_];
    __shared__ float s_emb[D1_];

    const int* src = edges + (size_t)g * 2 * E_;
    const int* dst = src + E_;
    const int4* src4 = (const int4*)src;
    const int4* dst4 = (const int4*)dst;

    s_deg[tid] = 1;                 // self loop
    s_w[tid]   = 0.f;
    __syncthreads();

    // E_ = 2048 -> exactly one int4 per thread
    const int4 d4 = __ldg(&dst4[tid]);
    atomicAdd(&s_deg[d4.x], 1);
    atomicAdd(&s_deg[d4.y], 1);
    atomicAdd(&s_deg[d4.z], 1);
    atomicAdd(&s_deg[d4.w], 1);
    __syncthreads();

    s_dinv[tid] = rsqrtf((float)s_deg[tid]);
    __syncthreads();

    const int4 s4 = __ldg(&src4[tid]);
    atomicAdd(&s_w[s4.x], s_dinv[d4.x]);
    atomicAdd(&s_w[s4.y], s_dinv[d4.y]);
    atomicAdd(&s_w[s4.z], s_dinv[d4.z]);
    atomicAdd(&s_w[s4.w], s_dinv[d4.w]);
    __syncthreads();

    // w[n] = dinv[n]*(sdst[n] + dinv[n]); own-slot rewrite, resync after
    const float wn_self = s_dinv[tid] * (s_w[tid] + s_dinv[tid]);
    __syncthreads();
    s_w[tid] = wn_self;
    __syncthreads();

    // v[f] = sum_n w[n]*x[n,f] : 32 row-groups x 16 float4-lanes
    const int lane = tid & 15;          // float4 column 0..15
    const int grp  = tid >> 4;          // 0..31
    const float4* x4 = (const float4*)(features + (size_t)g * N_ * F_);
    float4 acc = make_float4(0.f, 0.f, 0.f, 0.f);
    #pragma unroll
    for (int j = 0; j < 16; j++) {
        const int n = grp + j * 32;
        const float wn = s_w[n];
        const float4 xv = __ldg(&x4[n * 16 + lane]);
        acc.x += wn * xv.x;
        acc.y += wn * xv.y;
        acc.z += wn * xv.z;
        acc.w += wn * xv.w;
    }
    float* pp = &s_part[grp * F_ + lane * 4];
    pp[0] = acc.x; pp[1] = acc.y; pp[2] = acc.z; pp[3] = acc.w;
    __syncthreads();

    if (tid < F_) {
        float v = 0.f;
        #pragma unroll
        for (int gr = 0; gr < 32; gr++) v += s_part[gr * F_ + tid];
        s_v[tid] = v;
    }
    __syncthreads();

    // emb[d] = (sum_f v[f]*W1[f,d] + 512*b1[d]) / 16
    if (tid < D1_) {
        float a = 512.0f * __ldg(&b1[tid]);
        #pragma unroll
        for (int ff = 0; ff < F_; ff++)
            a += s_v[ff] * __ldg(&W1[ff * D1_ + tid]);
        s_emb[tid] = a * (1.0f / 16.0f);
    }
    __syncthreads();

    // t1[g,d'] = dinv2[g] * sum_d emb[d]*conv1_W[d,d']
    if (tid < D1_) {
        const float dv = __ldg(&g_dinv2[g]);
        float a = 0.f;
        #pragma unroll 16
        for (int d = 0; d < D1_; d++)
            a += s_emb[d] * __ldg(&conv1_W[d * D1_ + tid]);
        g_t1[g * D1_ + tid] = dv * a;
    }
}

// ---------------- conv1 gather + relu + mu matmul (fused) -----------------
__global__ void __launch_bounds__(128) gather1_kernel(
    const float* __restrict__ conv1_b,
    const float* __restrict__ mu_W)
{
    const int m = blockIdx.x;
    const int d = threadIdx.x;          // 128
    __shared__ float s_row[D1_];

    const int beg = g_off[m], end = g_off[m + 1];
    float acc = g_t1[m * D1_ + d];      // self loop
    int i = beg;
    for (; i + 4 <= end; i += 4) {
        const int a0 = __ldg(&g_srcbuf[i]);
        const int a1 = __ldg(&g_srcbuf[i + 1]);
        const int a2 = __ldg(&g_srcbuf[i + 2]);
        const int a3 = __ldg(&g_srcbuf[i + 3]);
        acc += __ldg(&g_t1[a0 * D1_ + d]) + __ldg(&g_t1[a1 * D1_ + d])
             + __ldg(&g_t1[a2 * D1_ + d]) + __ldg(&g_t1[a3 * D1_ + d]);
    }
    for (; i < end; i++)
        acc += __ldg(&g_t1[__ldg(&g_srcbuf[i]) * D1_ + d]);

    const float dv = g_dinv2[m];
    s_row[d] = fmaxf(dv * acc + __ldg(&conv1_b[d]), 0.f);
    __syncthreads();

    if (d < D2_) {
        float a = 0.f;
        #pragma unroll 16
        for (int ff = 0; ff < D1_; ff++)
            a += s_row[ff] * __ldg(&mu_W[ff * D2_ + d]);
        g_t2[m * D2_ + d] = dv * a;
    }
}

// ---------------- mu gather + classifier + log_softmax (fused) ------------
__global__ void __launch_bounds__(64) gather2_kernel(
    const float* __restrict__ mu_b,
    const float* __restrict__ clf_W,
    const float* __restrict__ clf_b,
    float* __restrict__ out)
{
    const int m = blockIdx.x;
    const int d = threadIdx.x;          // 64
    __shared__ float s_mu[D2_];

    const int beg = g_off[m], end = g_off[m + 1];
    float acc = g_t2[m * D2_ + d];      // self loop
    int i = beg;
    for (; i + 4 <= end; i += 4) {
        const int a0 = __ldg(&g_srcbuf[i]);
        const int a1 = __ldg(&g_srcbuf[i + 1]);
        const int a2 = __ldg(&g_srcbuf[i + 2]);
        const int a3 = __ldg(&g_srcbuf[i + 3]);
        acc += __ldg(&g_t2[a0 * D2_ + d]) + __ldg(&g_t2[a1 * D2_ + d])
             + __ldg(&g_t2[a2 * D2_ + d]) + __ldg(&g_t2[a3 * D2_ + d]);
    }
    for (; i < end; i++)
        acc += __ldg(&g_t2[__ldg(&g_srcbuf[i]) * D2_ + d]);

    s_mu[d] = g_dinv2[m] * acc + __ldg(&mu_b[d]);
    __syncthreads();

    if (d < L_) {                       // warp 0: 32 logits + log_softmax
        float a = __ldg(&clf_b[d]);
        #pragma unroll
        for (int ff = 0; ff < D2_; ff++)
            a += s_mu[ff] * __ldg(&clf_W[ff * L_ + d]);
        float mx = a;
        #pragma unroll
        for (int o = 16; o > 0; o >>= 1)
            mx = fmaxf(mx, __shfl_xor_sync(0xffffffffu, mx, o));
        const float ex = expf(a - mx);
        float sm = ex;
        #pragma unroll
        for (int o = 16; o > 0; o >>= 1)
            sm += __shfl_xor_sync(0xffffffffu, sm, o);
        out[m * L_ + d] = a - mx - logf(sm);
    }
}

// --------------------------------------------------------------------------
extern "C" void kernel_launch(void* const* d_in, const int* in_sizes, int n_in,
                              void* d_out, int out_size)
{
    const float* features = (const float*)d_in[0];
    const int*   edges    = (const int*)  d_in[1];
    const int*   pos_e    = (const int*)  d_in[2];
    const float* W1       = (const float*)d_in[3];
    const float* b1       = (const float*)d_in[4];
    // d_in[5..8]: fc1_W, fc1_b, fc2_W, fc2_b — mathematically dead (softmax rows sum to 1)
    const float* conv1_W  = (const float*)d_in[9];
    const float* conv1_b  = (const float*)d_in[10];
    const float* mu_W     = (const float*)d_in[11];
    const float* mu_b     = (const float*)d_in[12];
    const float* clf_W    = (const float*)d_in[13];
    const float* clf_b    = (const float*)d_in[14];
    float* out = (float*)d_out;

    build_kernel  <<<1, 512>>>(pos_e);
    sage_kernel   <<<G_, 512>>>(features, edges, W1, b1, conv1_W);
    gather1_kernel<<<G_, 128>>>(conv1_b, mu_W);
    gather2_kernel<<<G_, 64>>>(mu_b, clf_W, clf_b, out);
}

// round 4
// speedup vs baseline: 1.4333x; 1.3710x over previous
#include <cuda_runtime.h>

// Problem constants
#define G_   512
#define N_   512
#define E_   2048
#define F_   64
#define D1_  128
#define D2_  64
#define L_   32
#define P_   16384
#define NB_  32          // build blocks (P_/512)
#define MAXDEG_ 256

// ---------------- device scratch (no allocations allowed) ----------------
__device__ float g_t1[G_ * D1_];      // dinv2[g] * (emb[g,:] @ conv1_W)
__device__ float g_t2[G_ * D2_];      // dinv2[m] * (relu_row @ mu_W)
__device__ int   g_off[G_ + 1];
__device__ float g_dinv2[G_];
__device__ int   g_srcbuf[P_];
__device__ int   g_partial[NB_][G_];  // per-block dst histograms
__device__ int   g_base[NB_][G_];     // per-(block,dst) starting slot

// ---------------- CSR build: count (privatized, no global atomics) --------
__global__ void __launch_bounds__(512) count_kernel(const int* __restrict__ pos_edges)
{
    __shared__ int s_cnt[G_];
    const int b = blockIdx.x, tid = threadIdx.x;
    s_cnt[tid] = 0;
    __syncthreads();
    const int d = __ldg(&pos_edges[P_ + b * 512 + tid]);
    atomicAdd(&s_cnt[d], 1);
    __syncthreads();
    g_partial[b][tid] = s_cnt[tid];
}

// ---------------- CSR build: scan + per-block bases -----------------------
__global__ void __launch_bounds__(512) scan_kernel()
{
    const int tid = threadIdx.x;
    int part[NB_];
    int c = 0;
    #pragma unroll
    for (int b = 0; b < NB_; b++) { part[b] = g_partial[b][tid]; c += part[b]; }
    g_dinv2[tid] = rsqrtf((float)(c + 1));       // +1 self loop

    // exclusive scan of c over 512 threads (warp shuffle + warp-sum scan)
    const int lane = tid & 31, w = tid >> 5;
    int v = c;
    #pragma unroll
    for (int o = 1; o < 32; o <<= 1) {
        int t = __shfl_up_sync(0xffffffffu, v, o);
        if (lane >= o) v += t;
    }
    __shared__ int wsum[16];
    if (lane == 31) wsum[w] = v;
    __syncthreads();
    if (tid < 16) {
        int x = wsum[tid];
        #pragma unroll
        for (int o = 1; o < 16; o <<= 1) {
            int t = __shfl_up_sync(0x0000ffffu, x, o);
            if (tid >= o) x += t;
        }
        wsum[tid] = x;
    }
    __syncthreads();
    const int incl = v + (w > 0 ? wsum[w - 1] : 0);
    const int excl = incl - c;
    g_off[tid + 1] = incl;
    if (tid == 0) g_off[0] = 0;

    int base = excl;
    #pragma unroll
    for (int b = 0; b < NB_; b++) { g_base[b][tid] = base; base += part[b]; }
}

// ---------------- CSR build: scatter (smem rank counters only) ------------
__global__ void __launch_bounds__(512) scatter_kernel(const int* __restrict__ pos_edges)
{
    __shared__ int s_fill[G_];
    const int b = blockIdx.x, tid = threadIdx.x;
    s_fill[tid] = 0;
    __syncthreads();
    const int e = b * 512 + tid;
    const int d = __ldg(&pos_edges[P_ + e]);
    const int s = __ldg(&pos_edges[e]);
    const int r = atomicAdd(&s_fill[d], 1);      // rank within block
    g_srcbuf[g_base[b][d] + r] = s;
}

// ---------------- SAGE per graph, collapsed to rank-1 form ----------------
// emb[g,:] = ((w^T X_g) @ W1 + 512*b1) / 16 ; t1[g,:] = dinv2[g]*(emb @ conv1_W)
__global__ void __launch_bounds__(512) sage_kernel(
    const float* __restrict__ features,
    const int*   __restrict__ edges,
    const float* __restrict__ W1,
    const float* __restrict__ b1,
    const float* __restrict__ conv1_W)
{
    const int g   = blockIdx.x;
    const int tid = threadIdx.x;

    __shared__ float s_dinv[N_];
    __shared__ float s_w[N_];
    __shared__ int   s_deg[N_];
    __shared__ float s_part[32 * F_];   // 2048 floats, reused across stages
    __shared__ float s_v[F_];
    __shared__ float s_emb[D1_];

    const int* src = edges + (size_t)g * 2 * E_;
    const int* dst = src + E_;
    const int4* src4 = (const int4*)src;
    const int4* dst4 = (const int4*)dst;

    s_deg[tid] = 1;                 // self loop
    s_w[tid]   = 0.f;
    __syncthreads();

    const int4 d4 = __ldg(&dst4[tid]);
    atomicAdd(&s_deg[d4.x], 1);
    atomicAdd(&s_deg[d4.y], 1);
    atomicAdd(&s_deg[d4.z], 1);
    atomicAdd(&s_deg[d4.w], 1);
    __syncthreads();

    s_dinv[tid] = rsqrtf((float)s_deg[tid]);
    __syncthreads();

    const int4 s4 = __ldg(&src4[tid]);
    atomicAdd(&s_w[s4.x], s_dinv[d4.x]);
    atomicAdd(&s_w[s4.y], s_dinv[d4.y]);
    atomicAdd(&s_w[s4.z], s_dinv[d4.z]);
    atomicAdd(&s_w[s4.w], s_dinv[d4.w]);
    __syncthreads();

    const float wn_self = s_dinv[tid] * (s_w[tid] + s_dinv[tid]);
    __syncthreads();
    s_w[tid] = wn_self;
    __syncthreads();

    // v[f] = sum_n w[n]*x[n,f] : 32 row-groups x 16 float4-lanes
    {
        const int lane = tid & 15;
        const int grp  = tid >> 4;
        const float4* x4 = (const float4*)(features + (size_t)g * N_ * F_);
        float4 acc = make_float4(0.f, 0.f, 0.f, 0.f);
        #pragma unroll
        for (int j = 0; j < 16; j++) {
            const int n = grp + j * 32;
            const float wn = s_w[n];
            const float4 xv = __ldg(&x4[n * 16 + lane]);
            acc.x += wn * xv.x;
            acc.y += wn * xv.y;
            acc.z += wn * xv.z;
            acc.w += wn * xv.w;
        }
        float* pp = &s_part[grp * F_ + lane * 4];
        pp[0] = acc.x; pp[1] = acc.y; pp[2] = acc.z; pp[3] = acc.w;
    }
    __syncthreads();
    if (tid < F_) {
        float v = 0.f;
        #pragma unroll
        for (int gr = 0; gr < 32; gr++) v += s_part[gr * F_ + tid];
        s_v[tid] = v;
    }
    __syncthreads();

    // emb: 512 threads = 128 d x 4 h, each 16 ff
    {
        const int d = tid & 127, h = tid >> 7;
        float a = 0.f;
        #pragma unroll
        for (int k = 0; k < 16; k++) {
            const int ff = h * 16 + k;
            a += s_v[ff] * __ldg(&W1[ff * D1_ + d]);
        }
        s_part[h * D1_ + d] = a;
    }
    __syncthreads();
    if (tid < D1_) {
        const float a = s_part[tid] + s_part[D1_ + tid] + s_part[2 * D1_ + tid]
                      + s_part[3 * D1_ + tid] + 512.0f * __ldg(&b1[tid]);
        s_emb[tid] = a * (1.0f / 16.0f);
    }
    __syncthreads();

    // t1: 512 threads = 128 d x 4 h, each 32 ff
    {
        const int d = tid & 127, h = tid >> 7;
        float a = 0.f;
        #pragma unroll
        for (int k = 0; k < 32; k++) {
            const int ff = h * 32 + k;
            a += s_emb[ff] * __ldg(&conv1_W[ff * D1_ + d]);
        }
        s_part[h * D1_ + d] = a;
    }
    __syncthreads();
    if (tid < D1_) {
        const float dv = __ldg(&g_dinv2[g]);
        g_t1[g * D1_ + tid] = dv * (s_part[tid] + s_part[D1_ + tid]
                                  + s_part[2 * D1_ + tid] + s_part[3 * D1_ + tid]);
    }
}

// ---------------- conv1 gather + relu + mu matmul (fused) -----------------
__global__ void __launch_bounds__(512) gather1_kernel(
    const float* __restrict__ conv1_b,
    const float* __restrict__ mu_W)
{
    const int m   = blockIdx.x;
    const int tid = threadIdx.x;
    __shared__ float s_part[8 * D2_];     // 512 floats (also holds 4*128)
    __shared__ float s_row[D1_];
    __shared__ int   s_idx[MAXDEG_];

    const int beg = g_off[m], end = g_off[m + 1];
    int deg = end - beg;
    if (deg > MAXDEG_) deg = MAXDEG_;     // statistically unreachable; safety
    for (int i = tid; i < deg; i += 512) s_idx[i] = __ldg(&g_srcbuf[beg + i]);
    __syncthreads();

    // neighbor sum: 4 slices x 128 cols
    {
        const int d = tid & 127, slice = tid >> 7;
        float acc = 0.f;
        for (int i = slice; i < deg; i += 4)
            acc += __ldg(&g_t1[s_idx[i] * D1_ + d]);
        s_part[slice * D1_ + d] = acc;
    }
    __syncthreads();
    const float dv = g_dinv2[m];
    if (tid < D1_) {
        const float tot = s_part[tid] + s_part[D1_ + tid] + s_part[2 * D1_ + tid]
                        + s_part[3 * D1_ + tid] + g_t1[m * D1_ + tid];
        s_row[tid] = fmaxf(dv * tot + __ldg(&conv1_b[tid]), 0.f);
    }
    __syncthreads();

    // t2 = row @ mu_W : 64 d2 x 8 h, each 16 ff
    {
        const int d2 = tid & 63, h = tid >> 6;
        float a = 0.f;
        #pragma unroll
        for (int k = 0; k < 16; k++) {
            const int ff = h * 16 + k;
            a += s_row[ff] * __ldg(&mu_W[ff * D2_ + d2]);
        }
        s_part[h * D2_ + d2] = a;
    }
    __syncthreads();
    if (tid < D2_) {
        float t = 0.f;
        #pragma unroll
        for (int hh = 0; hh < 8; hh++) t += s_part[hh * D2_ + tid];
        g_t2[m * D2_ + tid] = dv * t;
    }
}

// ---------------- mu gather + classifier + log_softmax (fused) ------------
__global__ void __launch_bounds__(512) gather2_kernel(
    const float* __restrict__ mu_b,
    const float* __restrict__ clf_W,
    const float* __restrict__ clf_b,
    float* __restrict__ out)
{
    const int m   = blockIdx.x;
    const int tid = threadIdx.x;
    __shared__ float s_part[8 * D2_];
    __shared__ float s_mu[D2_];
    __shared__ float s_lp[8 * L_];
    __shared__ int   s_idx[MAXDEG_];

    const int beg = g_off[m], end = g_off[m + 1];
    int deg = end - beg;
    if (deg > MAXDEG_) deg = MAXDEG_;     // statistically unreachable; safety
    for (int i = tid; i < deg; i += 512) s_idx[i] = __ldg(&g_srcbuf[beg + i]);
    __syncthreads();

    // neighbor sum: 8 slices x 64 cols
    {
        const int d = tid & 63, slice = tid >> 6;
        float acc = 0.f;
        for (int i = slice; i < deg; i += 8)
            acc += __ldg(&g_t2[s_idx[i] * D2_ + d]);
        s_part[slice * D2_ + d] = acc;
    }
    __syncthreads();
    if (tid < D2_) {
        float tot = g_t2[m * D2_ + tid];
        #pragma unroll
        for (int s = 0; s < 8; s++) tot += s_part[s * D2_ + tid];
        s_mu[tid] = g_dinv2[m] * tot + __ldg(&mu_b[tid]);
    }
    __syncthreads();

    // logits: 32 l x 8 h, each 8 ff
    if (tid < 256) {
        const int l = tid & 31, h = tid >> 5;
        float a = 0.f;
        #pragma unroll
        for (int k = 0; k < 8; k++) {
            const int ff = h * 8 + k;
            a += s_mu[ff] * __ldg(&clf_W[ff * L_ + l]);
        }
        s_lp[h * L_ + l] = a;
    }
    __syncthreads();
    if (tid < L_) {                 // warp 0: reduce + log_softmax
        float a = __ldg(&clf_b[tid]);
        #pragma unroll
        for (int h = 0; h < 8; h++) a += s_lp[h * L_ + tid];
        float mx = a;
        #pragma unroll
        for (int o = 16; o > 0; o >>= 1)
            mx = fmaxf(mx, __shfl_xor_sync(0xffffffffu, mx, o));
        const float ex = expf(a - mx);
        float sm = ex;
        #pragma unroll
        for (int o = 16; o > 0; o >>= 1)
            sm += __shfl_xor_sync(0xffffffffu, sm, o);
        out[m * L_ + tid] = a - mx - logf(sm);
    }
}

// --------------------------------------------------------------------------
extern "C" void kernel_launch(void* const* d_in, const int* in_sizes, int n_in,
                              void* d_out, int out_size)
{
    const float* features = (const float*)d_in[0];
    const int*   edges    = (const int*)  d_in[1];
    const int*   pos_e    = (const int*)  d_in[2];
    const float* W1       = (const float*)d_in[3];
    const float* b1       = (const float*)d_in[4];
    // d_in[5..8]: fc1_W, fc1_b, fc2_W, fc2_b — mathematically dead (softmax rows sum to 1)
    const float* conv1_W  = (const float*)d_in[9];
    const float* conv1_b  = (const float*)d_in[10];
    const float* mu_W     = (const float*)d_in[11];
    const float* mu_b     = (const float*)d_in[12];
    const float* clf_W    = (const float*)d_in[13];
    const float* clf_b    = (const float*)d_in[14];
    float* out = (float*)d_out;

    count_kernel  <<<NB_, 512>>>(pos_e);
    scan_kernel   <<<1,   512>>>();
    scatter_kernel<<<NB_, 512>>>(pos_e);
    sage_kernel   <<<G_,  512>>>(features, edges, W1, b1, conv1_W);
    gather1_kernel<<<G_,  512>>>(conv1_b, mu_W);
    gather2_kernel<<<G_,  512>>>(mu_b, clf_W, clf_b, out);
}

// round 6
// speedup vs baseline: 1.4375x; 1.0029x over previous
#include <cuda_runtime.h>

// Problem constants
#define G_   512
#define N_   512
#define E_   2048
#define F_   64
#define D1_  128
#define D2_  64
#define L_   32
#define P_   16384
#define NB_  32          // build blocks (P_/512)
#define MAXDEG_ 256

// ---------------- device scratch (no allocations allowed) ----------------
__device__ float g_w[G_ * N_];        // per-node rank-1 weights
__device__ float g_t1[G_ * D1_];      // dinv2[g] * (emb[g,:] @ conv1_W)
__device__ float g_t2[G_ * D2_];      // dinv2[m] * (relu_row @ mu_W)
__device__ int   g_off[G_ + 1];
__device__ float g_dinv2[G_];
__device__ int   g_srcbuf[P_];
__device__ int   g_partial[NB_][G_];  // per-block dst histograms
__device__ int   g_base[NB_][G_];     // per-(block,dst) starting slot

// ---------------- CSR build: count (privatized, no global atomics) --------
__global__ void __launch_bounds__(512) count_kernel(const int* __restrict__ pos_edges)
{
    __shared__ int s_cnt[G_];
    const int b = blockIdx.x, tid = threadIdx.x;
    s_cnt[tid] = 0;
    __syncthreads();
    const int d = __ldg(&pos_edges[P_ + b * 512 + tid]);
    atomicAdd(&s_cnt[d], 1);
    __syncthreads();
    g_partial[b][tid] = s_cnt[tid];
}

// ---------------- CSR build: scan + per-block bases -----------------------
__global__ void __launch_bounds__(512) scan_kernel()
{
    const int tid = threadIdx.x;
    int part[NB_];
    int c = 0;
    #pragma unroll
    for (int b = 0; b < NB_; b++) { part[b] = g_partial[b][tid]; c += part[b]; }
    g_dinv2[tid] = rsqrtf((float)(c + 1));       // +1 self loop

    // exclusive scan of c over 512 threads (warp shuffle + warp-sum scan)
    const int lane = tid & 31, w = tid >> 5;
    int v = c;
    #pragma unroll
    for (int o = 1; o < 32; o <<= 1) {
        int t = __shfl_up_sync(0xffffffffu, v, o);
        if (lane >= o) v += t;
    }
    __shared__ int wsum[16];
    if (lane == 31) wsum[w] = v;
    __syncthreads();
    if (tid < 16) {
        int x = wsum[tid];
        #pragma unroll
        for (int o = 1; o < 16; o <<= 1) {
            int t = __shfl_up_sync(0x0000ffffu, x, o);
            if (tid >= o) x += t;
        }
        wsum[tid] = x;
    }
    __syncthreads();
    const int incl = v + (w > 0 ? wsum[w - 1] : 0);
    const int excl = incl - c;
    g_off[tid + 1] = incl;
    if (tid == 0) g_off[0] = 0;

    int base = excl;
    #pragma unroll
    for (int b = 0; b < NB_; b++) { g_base[b][tid] = base; base += part[b]; }
}

// ---------------- CSR build: scatter (smem rank counters only) ------------
__global__ void __launch_bounds__(512) scatter_kernel(const int* __restrict__ pos_edges)
{
    __shared__ int s_fill[G_];
    const int b = blockIdx.x, tid = threadIdx.x;
    s_fill[tid] = 0;
    __syncthreads();
    const int e = b * 512 + tid;
    const int d = __ldg(&pos_edges[P_ + e]);
    const int s = __ldg(&pos_edges[e]);
    const int r = atomicAdd(&s_fill[d], 1);      // rank within block
    g_srcbuf[g_base[b][d] + r] = s;
}

// ---------------- per-graph edge weights (hoisted prologue) ---------------
// w[n] = dinv[n]*(sum_{e:src=n} dinv[dst_e] + dinv[n])
__global__ void __launch_bounds__(512) w_kernel(const int* __restrict__ edges)
{
    const int g   = blockIdx.x;
    const int tid = threadIdx.x;

    __shared__ float s_dinv[N_];
    __shared__ float s_acc[N_];
    __shared__ int   s_deg[N_];

    const int* src = edges + (size_t)g * 2 * E_;
    const int* dst = src + E_;
    const int4* src4 = (const int4*)src;
    const int4* dst4 = (const int4*)dst;

    s_deg[tid] = 1;                 // self loop
    s_acc[tid] = 0.f;
    __syncthreads();

    const int4 d4 = __ldg(&dst4[tid]);
    atomicAdd(&s_deg[d4.x], 1);
    atomicAdd(&s_deg[d4.y], 1);
    atomicAdd(&s_deg[d4.z], 1);
    atomicAdd(&s_deg[d4.w], 1);
    __syncthreads();

    s_dinv[tid] = rsqrtf((float)s_deg[tid]);
    __syncthreads();

    const int4 s4 = __ldg(&src4[tid]);
    atomicAdd(&s_acc[s4.x], s_dinv[d4.x]);
    atomicAdd(&s_acc[s4.y], s_dinv[d4.y]);
    atomicAdd(&s_acc[s4.z], s_dinv[d4.z]);
    atomicAdd(&s_acc[s4.w], s_dinv[d4.w]);
    __syncthreads();

    g_w[g * N_ + tid] = s_dinv[tid] * (s_acc[tid] + s_dinv[tid]);
}

// ---------------- SAGE streaming + GEMV tail ------------------------------
// v[f] = sum_n w[n]*x[n,f]; emb = (v@W1 + 512*b1)/16; t1 = dinv2*(emb@conv1_W)
__global__ void __launch_bounds__(512, 4) sage_kernel(
    const float* __restrict__ features,
    const float* __restrict__ W1,
    const float* __restrict__ b1,
    const float* __restrict__ conv1_W)
{
    const int g   = blockIdx.x;
    const int tid = threadIdx.x;

    __shared__ float s_w[N_];
    __shared__ float s_part[32 * F_];   // 2048 floats, reused across stages
    __shared__ float s_v[F_];
    __shared__ float s_emb[D1_];

    s_w[tid] = g_w[g * N_ + tid];
    __syncthreads();

    // v[f] = sum_n w[n]*x[n,f] : 32 row-groups x 16 float4-lanes
    {
        const int lane = tid & 15;
        const int grp  = tid >> 4;
        const float4* x4 = (const float4*)(features + (size_t)g * N_ * F_);
        float4 acc = make_float4(0.f, 0.f, 0.f, 0.f);
        #pragma unroll
        for (int j = 0; j < 16; j++) {
            const int n = grp + j * 32;
            const float wn = s_w[n];
            const float4 xv = __ldg(&x4[n * 16 + lane]);
            acc.x += wn * xv.x;
            acc.y += wn * xv.y;
            acc.z += wn * xv.z;
            acc.w += wn * xv.w;
        }
        float* pp = &s_part[grp * F_ + lane * 4];
        pp[0] = acc.x; pp[1] = acc.y; pp[2] = acc.z; pp[3] = acc.w;
    }
    __syncthreads();
    if (tid < F_) {
        float v = 0.f;
        #pragma unroll
        for (int gr = 0; gr < 32; gr++) v += s_part[gr * F_ + tid];
        s_v[tid] = v;
    }
    __syncthreads();

    // emb: 512 threads = 128 d x 4 h, each 16 ff
    {
        const int d = tid & 127, h = tid >> 7;
        float a = 0.f;
        #pragma unroll
        for (int k = 0; k < 16; k++) {
            const int ff = h * 16 + k;
            a += s_v[ff] * __ldg(&W1[ff * D1_ + d]);
        }
        s_part[h * D1_ + d] = a;
    }
    __syncthreads();
    if (tid < D1_) {
        const float a = s_part[tid] + s_part[D1_ + tid] + s_part[2 * D1_ + tid]
                      + s_part[3 * D1_ + tid] + 512.0f * __ldg(&b1[tid]);
        s_emb[tid] = a * (1.0f / 16.0f);
    }
    __syncthreads();

    // t1: 512 threads = 128 d x 4 h, each 32 ff
    {
        const int d = tid & 127, h = tid >> 7;
        float a = 0.f;
        #pragma unroll
        for (int k = 0; k < 32; k++) {
            const int ff = h * 32 + k;
            a += s_emb[ff] * __ldg(&conv1_W[ff * D1_ + d]);
        }
        s_part[h * D1_ + d] = a;
    }
    __syncthreads();
    if (tid < D1_) {
        const float dv = __ldg(&g_dinv2[g]);
        g_t1[g * D1_ + tid] = dv * (s_part[tid] + s_part[D1_ + tid]
                                  + s_part[2 * D1_ + tid] + s_part[3 * D1_ + tid]);
    }
}

// ---------------- conv1 gather + relu + mu matmul (fused) -----------------
__global__ void __launch_bounds__(512) gather1_kernel(
    const float* __restrict__ conv1_b,
    const float* __restrict__ mu_W)
{
    const int m   = blockIdx.x;
    const int tid = threadIdx.x;
    __shared__ float s_part[8 * D2_];     // 512 floats (also holds 4*128)
    __shared__ float s_row[D1_];
    __shared__ int   s_idx[MAXDEG_];

    const int beg = g_off[m], end = g_off[m + 1];
    int deg = end - beg;
    if (deg > MAXDEG_) deg = MAXDEG_;     // statistically unreachable; safety
    for (int i = tid; i < deg; i += 512) s_idx[i] = __ldg(&g_srcbuf[beg + i]);
    __syncthreads();

    // neighbor sum: 4 slices x 128 cols, unroll-4 for MLP
    {
        const int d = tid & 127, slice = tid >> 7;
        float acc = 0.f;
        #pragma unroll 4
        for (int i = slice; i < deg; i += 4)
            acc += __ldg(&g_t1[s_idx[i] * D1_ + d]);
        s_part[slice * D1_ + d] = acc;
    }
    __syncthreads();
    const float dv = g_dinv2[m];
    if (tid < D1_) {
        const float tot = s_part[tid] + s_part[D1_ + tid] + s_part[2 * D1_ + tid]
                        + s_part[3 * D1_ + tid] + g_t1[m * D1_ + tid];
        s_row[tid] = fmaxf(dv * tot + __ldg(&conv1_b[tid]), 0.f);
    }
    __syncthreads();

    // t2 = row @ mu_W : 64 d2 x 8 h, each 16 ff
    {
        const int d2 = tid & 63, h = tid >> 6;
        float a = 0.f;
        #pragma unroll
        for (int k = 0; k < 16; k++) {
            const int ff = h * 16 + k;
            a += s_row[ff] * __ldg(&mu_W[ff * D2_ + d2]);
        }
        s_part[h * D2_ + d2] = a;
    }
    __syncthreads();
    if (tid < D2_) {
        float t = 0.f;
        #pragma unroll
        for (int hh = 0; hh < 8; hh++) t += s_part[hh * D2_ + tid];
        g_t2[m * D2_ + tid] = dv * t;
    }
}

// ---------------- mu gather + classifier + log_softmax (fused) ------------
__global__ void __launch_bounds__(512) gather2_kernel(
    const float* __restrict__ mu_b,
    const float* __restrict__ clf_W,
    const float* __restrict__ clf_b,
    float* __restrict__ out)
{
    const int m   = blockIdx.x;
    const int tid = threadIdx.x;
    __shared__ float s_part[8 * D2_];
    __shared__ float s_mu[D2_];
    __shared__ float s_lp[8 * L_];
    __shared__ int   s_idx[MAXDEG_];

    const int beg = g_off[m], end = g_off[m + 1];
    int deg = end - beg;
    if (deg > MAXDEG_) deg = MAXDEG_;     // statistically unreachable; safety
    for (int i = tid; i < deg; i += 512) s_idx[i] = __ldg(&g_srcbuf[beg + i]);
    __syncthreads();

    // neighbor sum: 8 slices x 64 cols, unroll-4 for MLP
    {
        const int d = tid & 63, slice = tid >> 6;
        float acc = 0.f;
        #pragma unroll 4
        for (int i = slice; i < deg; i += 8)
            acc += __ldg(&g_t2[s_idx[i] * D2_ + d]);
        s_part[slice * D2_ + d] = acc;
    }
    __syncthreads();
    if (tid < D2_) {
        float tot = g_t2[m * D2_ + tid];
        #pragma unroll
        for (int s = 0; s < 8; s++) tot += s_part[s * D2_ + tid];
        s_mu[tid] = g_dinv2[m] * tot + __ldg(&mu_b[tid]);
    }
    __syncthreads();

    // logits: 32 l x 8 h, each 8 ff
    if (tid < 256) {
        const int l = tid & 31, h = tid >> 5;
        float a = 0.f;
        #pragma unroll
        for (int k = 0; k < 8; k++) {
            const int ff = h * 8 + k;
            a += s_mu[ff] * __ldg(&clf_W[ff * L_ + l]);
        }
        s_lp[h * L_ + l] = a;
    }
    __syncthreads();
    if (tid < L_) {                 // warp 0: reduce + log_softmax
        float a = __ldg(&clf_b[tid]);
        #pragma unroll
        for (int h = 0; h < 8; h++) a += s_lp[h * L_ + tid];
        float mx = a;
        #pragma unroll
        for (int o = 16; o > 0; o >>= 1)
            mx = fmaxf(mx, __shfl_xor_sync(0xffffffffu, mx, o));
        const float ex = expf(a - mx);
        float sm = ex;
        #pragma unroll
        for (int o = 16; o > 0; o >>= 1)
            sm += __shfl_xor_sync(0xffffffffu, sm, o);
        out[m * L_ + tid] = a - mx - logf(sm);
    }
}

// --------------------------------------------------------------------------
extern "C" void kernel_launch(void* const* d_in, const int* in_sizes, int n_in,
                              void* d_out, int out_size)
{
    const float* features = (const float*)d_in[0];
    const int*   edges    = (const int*)  d_in[1];
    const int*   pos_e    = (const int*)  d_in[2];
    const float* W1       = (const float*)d_in[3];
    const float* b1       = (const float*)d_in[4];
    // d_in[5..8]: fc1_W, fc1_b, fc2_W, fc2_b — mathematically dead (softmax rows sum to 1)
    const float* conv1_W  = (const float*)d_in[9];
    const float* conv1_b  = (const float*)d_in[10];
    const float* mu_W     = (const float*)d_in[11];
    const float* mu_b     = (const float*)d_in[12];
    const float* clf_W    = (const float*)d_in[13];
    const float* clf_b    = (const float*)d_in[14];
    float* out = (float*)d_out;

    // CSR-build chain first (small kernels), then the long feature pipeline.
    count_kernel  <<<NB_, 512>>>(pos_e);
    scan_kernel   <<<1,   512>>>();
    scatter_kernel<<<NB_, 512>>>(pos_e);
    w_kernel      <<<G_,  512>>>(edges);
    sage_kernel   <<<G_,  512>>>(features, W1, b1, conv1_W);
    gather1_kernel<<<G_,  512>>>(conv1_b, mu_W);
    gather2_kernel<<<G_,  512>>>(mu_b, clf_W, clf_b, out);
}